// round 12
// baseline (speedup 1.0000x reference)
#include <cuda_runtime.h>
#include <cuda_fp16.h>
#include <cstdint>
#include <cstddef>

#define NND 50000
#define NED 800000
#define F0 1433
#define KP 1472            // 23 * 64
#define NKT 23
#define F1 256
#define F2 32
#define NBS 196            // scan blocks: 196*256 = 50176

#define SA_Q 32.0f
#define SW_Q 2000.0f
#define DEQ  (1.0f / (SA_Q * SW_Q))

// ---------------- device scratch -------------------------------------------
__device__ float g_csrc[NND];
__device__ float g_cdst[NND];
__device__ __half g_h1[(size_t)NND * F1];
__device__ __half g_h2[(size_t)NND * F2];
__device__ float g_h3[(size_t)NND * 8];
__device__ int   g_is64;
__device__ int   g_degin[NND];
__device__ int   g_degout[NND];
__device__ int   g_off[NND + 1];
__device__ int   g_cur[NND];
__device__ int   g_srcl[NED];
__device__ int   g_bsum[NBS];
// W1^T as int8: [n=256][k=KP]
__device__ signed char g_Bq[(size_t)F1 * KP];

// ---------------- helpers ---------------------------------------------------
__device__ __forceinline__ int load_idx(const void* edge, int is64, long long lin) {
    if (is64) return (int)((const long long*)edge)[lin];
    return ((const int*)edge)[lin];
}
__device__ __forceinline__ void cpa16(uint32_t dst, const void* src) {
    asm volatile("cp.async.cg.shared.global [%0],[%1],16;" :: "r"(dst), "l"(src));
}
#define CP_COMMIT() asm volatile("cp.async.commit_group;")
#define CP_WAIT1()  asm volatile("cp.async.wait_group 1;" ::: "memory")

__device__ __forceinline__ void ldsm4(uint32_t& r0, uint32_t& r1, uint32_t& r2, uint32_t& r3, uint32_t a) {
    asm volatile("ldmatrix.sync.aligned.m8n8.x4.shared.b16 {%0,%1,%2,%3},[%4];"
                 : "=r"(r0), "=r"(r1), "=r"(r2), "=r"(r3) : "r"(a));
}
// int8 MMA: m16n8k32, s32 accumulate
__device__ __forceinline__ void mma_s8(int* c, const uint32_t* a, uint32_t b0, uint32_t b1) {
    asm volatile("mma.sync.aligned.m16n8k32.row.col.s32.s8.s8.s32 "
                 "{%0,%1,%2,%3},{%4,%5,%6,%7},{%8,%9},{%0,%1,%2,%3};"
                 : "+r"(c[0]), "+r"(c[1]), "+r"(c[2]), "+r"(c[3])
                 : "r"(a[0]), "r"(a[1]), "r"(a[2]), "r"(a[3]), "r"(b0), "r"(b1));
}
__device__ __forceinline__ uint32_t smem_u32(const void* p) {
    uint32_t a;
    asm("{ .reg .u64 t; cvta.to.shared.u64 t, %1; cvt.u32.u64 %0, t; }" : "=r"(a) : "l"(p));
    return a;
}
__device__ __forceinline__ uint32_t q4pack(float v0, float v1, float v2, float v3) {
    int q0 = __float2int_rn(fminf(fmaxf(v0 * SA_Q, -127.f), 127.f));
    int q1 = __float2int_rn(fminf(fmaxf(v1 * SA_Q, -127.f), 127.f));
    int q2 = __float2int_rn(fminf(fmaxf(v2 * SA_Q, -127.f), 127.f));
    int q3 = __float2int_rn(fminf(fmaxf(v3 * SA_Q, -127.f), 127.f));
    return (uint32_t)(q0 & 255) | ((uint32_t)(q1 & 255) << 8) |
           ((uint32_t)(q2 & 255) << 16) | ((uint32_t)(q3 & 255) << 24);
}

// ---------------- convW1: tiled transpose fp32 [K][N] -> int8 [N][KP] -------
__global__ __launch_bounds__(256)
void convW1_kernel(const float* __restrict__ W1) {
    __shared__ float t[32][33];
    int k0 = blockIdx.x * 32, n0 = blockIdx.y * 32;
    int tx = threadIdx.x & 31, ty = threadIdx.x >> 5;   // 32 x 8
    #pragma unroll
    for (int i = 0; i < 4; i++) {
        int k = k0 + ty + 8 * i;
        t[ty + 8 * i][tx] = (k < F0) ? W1[(size_t)k * F1 + n0 + tx] : 0.f;
    }
    __syncthreads();
    #pragma unroll
    for (int i = 0; i < 4; i++) {
        int n = n0 + ty + 8 * i;
        float w = t[tx][ty + 8 * i];
        int q = __float2int_rn(fminf(fmaxf(w * SW_Q, -127.f), 127.f));
        g_Bq[(size_t)n * KP + k0 + tx] = (signed char)q;
    }
}

// ---------------- zero_detect: detect int64 + zero degrees (s2 leg) ---------
__global__ void zero_detect_kernel(const void* edge) {
    int i = blockIdx.x * blockDim.x + threadIdx.x;
    if (i == 0) {
        const unsigned long long* p = (const unsigned long long*)edge;
        int ok = 1;
        #pragma unroll
        for (int j = 0; j < 16; j++)
            if (p[j] >= (unsigned long long)NND) ok = 0;
        g_is64 = ok;
    }
    if (i < NND) { g_degin[i] = 0; g_degout[i] = 0; }
}

__global__ void deg_kernel(const void* edge) {
    int is64 = g_is64;
    int stride = gridDim.x * blockDim.x;
    for (int e = blockIdx.x * blockDim.x + threadIdx.x; e < NED; e += stride) {
        int s = load_idx(edge, is64, e);
        int d = load_idx(edge, is64, (long long)NED + e);
        atomicAdd(&g_degout[s], 1);
        atomicAdd(&g_degin[d], 1);
    }
}

// ---------------- 2-kernel coalesced scan -----------------------------------
__global__ __launch_bounds__(256) void scanA_kernel() {
    __shared__ int sd[256];
    int t = threadIdx.x, b = blockIdx.x;
    int idx = b * 256 + t;
    int d = (idx < NND) ? g_degin[idx] : 0;
    sd[t] = d; __syncthreads();
    #pragma unroll
    for (int s = 1; s < 256; s <<= 1) {
        int v = (t >= s) ? sd[t - s] : 0;
        __syncthreads();
        sd[t] += v;
        __syncthreads();
    }
    if (idx < NND) g_off[idx] = sd[t] - d;     // block-exclusive
    if (t == 255) g_bsum[b] = sd[255];
}
__global__ __launch_bounds__(256) void scanC_kernel() {
    __shared__ int sd[256];
    int t = threadIdx.x, b = blockIdx.x;
    sd[t] = (t < b) ? g_bsum[t] : 0;
    __syncthreads();
    #pragma unroll
    for (int s = 128; s > 0; s >>= 1) {
        if (t < s) sd[t] += sd[t + s];
        __syncthreads();
    }
    int pre = sd[0];
    int idx = b * 256 + t;
    if (idx < NND) {
        int off = g_off[idx] + pre;
        g_off[idx] = off;
        g_cur[idx] = off;
        g_csrc[idx] = rsqrtf((float)max(g_degout[idx], 1));
        g_cdst[idx] = rsqrtf((float)max(g_degin[idx], 1));
    }
    if (idx == 0) g_off[NND] = NED;
}

__global__ void fill_kernel(const void* edge) {
    int is64 = g_is64;
    int stride = gridDim.x * blockDim.x;
    for (int e = blockIdx.x * blockDim.x + threadIdx.x; e < NED; e += stride) {
        int s = load_idx(edge, is64, e);
        int d = load_idx(edge, is64, (long long)NED + e);
        int pos = atomicAdd(&g_cur[d], 1);
        g_srcl[pos] = s;
    }
}

// ---------------- GEMM1: int8 mma.sync m16n8k32, M=128 N=256, 3-stage -------
#define ASTR 80                   /* 64 int8 + 16 pad */
#define SA_SZ (128 * ASTR)        /* 10240 */
#define SB_SZ (256 * ASTR)        /* 20480 */
#define STAGE (SA_SZ + SB_SZ)     /* 30720 */
#define SMEM_G1 (3 * STAGE)       /* 92160 */

extern __shared__ char g1s[];

__global__ __launch_bounds__(512, 1)
void gemm1_s8(const float* __restrict__ A, const signed char* __restrict__ Bq,
              __half* __restrict__ C)
{
    const int tid = threadIdx.x;
    const int l   = tid & 31;
    const int wid = tid >> 5;
    const int mw  = (wid & 1) * 64;
    const int nw  = (wid >> 1) * 32;
    const int bm  = blockIdx.x * 128;
    const uint32_t sb = smem_u32(g1s);

    // A ldg geometry: row = tid>>2 (128 rows), cg = tid&3 -> cols cg*16..+15
    const int a_row = tid >> 2, a_cg = tid & 3;
    const int a_grow = bm + a_row;
    const bool a_rv = (a_grow < NND);
    const float* a_base = A + (size_t)a_grow * F0 + a_cg * 16;

    int acc[4][4][4];
    #pragma unroll
    for (int t = 0; t < 4; t++)
        #pragma unroll
        for (int j = 0; j < 4; j++)
            #pragma unroll
            for (int q = 0; q < 4; q++) acc[t][j][q] = 0;

    float rA[16];
    auto ldgA = [&](int kt) {
        int c0 = kt * 64 + a_cg * 16;
        #pragma unroll
        for (int j = 0; j < 16; j++)
            rA[j] = (a_rv && (c0 + j) < F0) ? __ldg(a_base + kt * 64 + j) : 0.f;
    };
    auto stsA = [&](int buf) {
        uint32_t w0 = q4pack(rA[0],  rA[1],  rA[2],  rA[3]);
        uint32_t w1 = q4pack(rA[4],  rA[5],  rA[6],  rA[7]);
        uint32_t w2 = q4pack(rA[8],  rA[9],  rA[10], rA[11]);
        uint32_t w3 = q4pack(rA[12], rA[13], rA[14], rA[15]);
        *(uint4*)(g1s + buf * STAGE + a_row * ASTR + a_cg * 16) = make_uint4(w0, w1, w2, w3);
    };
    auto cpB = [&](int kt, int buf) {
        #pragma unroll
        for (int i = 0; i < 2; i++) {
            int ch = tid * 2 + i;                 // 0..1023
            int n = ch >> 2, c16 = ch & 3;
            uint32_t dst = sb + (uint32_t)(buf * STAGE + SA_SZ + n * ASTR + c16 * 16);
            cpa16(dst, Bq + (size_t)n * KP + kt * 64 + c16 * 16);
        }
    };

    // prologue
    ldgA(0); cpB(0, 0); CP_COMMIT();
    stsA(0);
    ldgA(1); cpB(1, 1); CP_COMMIT();

    const int      lrow = ((l >> 3) & 1) * 8 + (l & 7);
    const uint32_t acol = (uint32_t)((l >> 4) * 16);
    const uint32_t brow = (uint32_t)(nw + ((l >> 4) & 1) * 8 + (l & 7));
    const uint32_t bcol = (uint32_t)(((l >> 3) & 1) * 16);

    for (int kt = 0; kt < NKT; kt++) {
        CP_WAIT1();
        __syncthreads();
        if (kt + 1 < NKT) stsA((kt + 1) % 3);
        if (kt + 2 < NKT) { cpB(kt + 2, (kt + 2) % 3); ldgA(kt + 2); }
        CP_COMMIT();

        const int buf = kt % 3;
        const uint32_t sa  = sb + (uint32_t)(buf * STAGE);
        const uint32_t sbb = sa + SA_SZ;

        #pragma unroll
        for (int ks = 0; ks < 2; ks++) {          // two k32 steps per K=64 stage
            uint32_t bb[8];
            uint32_t ba = sbb + brow * ASTR + (uint32_t)(ks * 32) + bcol;
            ldsm4(bb[0], bb[1], bb[2], bb[3], ba);
            ldsm4(bb[4], bb[5], bb[6], bb[7], ba + 16 * ASTR);
            #pragma unroll
            for (int t = 0; t < 4; t++) {
                uint32_t aa[4];
                uint32_t aadr = sa + (uint32_t)((mw + t * 16 + lrow) * ASTR + ks * 32) + acol;
                ldsm4(aa[0], aa[1], aa[2], aa[3], aadr);
                mma_s8(acc[t][0], aa, bb[0], bb[1]);
                mma_s8(acc[t][1], aa, bb[2], bb[3]);
                mma_s8(acc[t][2], aa, bb[4], bb[5]);
                mma_s8(acc[t][3], aa, bb[6], bb[7]);
            }
        }
        __syncthreads();
    }

    // epilogue: dequant, store fp16
    #pragma unroll
    for (int t = 0; t < 4; t++) {
        int r0 = bm + mw + t * 16 + (l >> 2);
        #pragma unroll
        for (int half = 0; half < 2; half++) {
            int row = r0 + half * 8;
            if (row < NND) {
                #pragma unroll
                for (int j = 0; j < 4; j++) {
                    int col = nw + j * 8 + (l & 3) * 2;
                    __half2 v = __floats2half2_rn((float)acc[t][j][half * 2]     * DEQ,
                                                  (float)acc[t][j][half * 2 + 1] * DEQ);
                    *(__half2*)&C[(size_t)row * F1 + col] = v;
                }
            }
        }
    }
}

// ---------------- fusedA: agg256(h1*csrc[s]) + relu + GEMM2 -> h2 fp16 ------
__global__ __launch_bounds__(1024)
void fusedA_kernel(const __half* __restrict__ h1, const float* __restrict__ W2,
                   const float* __restrict__ b1, __half* __restrict__ h2,
                   const float* __restrict__ csrc, const float* __restrict__ cdst) {
    __shared__ float W2s[256 * 32];
    __shared__ float x1s[32][256];
    const int tid = threadIdx.x;
    for (int i = tid; i < 256 * 32; i += 1024) W2s[i] = W2[i];
    __syncthreads();

    const int wl   = tid >> 5;
    const int lane = tid & 31;
    const int node = blockIdx.x * 32 + wl;
    if (node >= NND) return;

    int i0 = g_off[node], i1 = g_off[node + 1];
    float a[8] = {0.f, 0.f, 0.f, 0.f, 0.f, 0.f, 0.f, 0.f};
    int i = i0;
    for (; i + 2 <= i1; i += 2) {
        int s0 = g_srcl[i], s1 = g_srcl[i + 1];
        float c0 = csrc[s0], c1 = csrc[s1];
        uint4 v0 = *(const uint4*)(h1 + (size_t)s0 * 256 + lane * 8);
        uint4 v1 = *(const uint4*)(h1 + (size_t)s1 * 256 + lane * 8);
        float2 f;
        f = __half22float2(*(__half2*)&v0.x); a[0] = fmaf(f.x, c0, a[0]); a[1] = fmaf(f.y, c0, a[1]);
        f = __half22float2(*(__half2*)&v0.y); a[2] = fmaf(f.x, c0, a[2]); a[3] = fmaf(f.y, c0, a[3]);
        f = __half22float2(*(__half2*)&v0.z); a[4] = fmaf(f.x, c0, a[4]); a[5] = fmaf(f.y, c0, a[5]);
        f = __half22float2(*(__half2*)&v0.w); a[6] = fmaf(f.x, c0, a[6]); a[7] = fmaf(f.y, c0, a[7]);
        f = __half22float2(*(__half2*)&v1.x); a[0] = fmaf(f.x, c1, a[0]); a[1] = fmaf(f.y, c1, a[1]);
        f = __half22float2(*(__half2*)&v1.y); a[2] = fmaf(f.x, c1, a[2]); a[3] = fmaf(f.y, c1, a[3]);
        f = __half22float2(*(__half2*)&v1.z); a[4] = fmaf(f.x, c1, a[4]); a[5] = fmaf(f.y, c1, a[5]);
        f = __half22float2(*(__half2*)&v1.w); a[6] = fmaf(f.x, c1, a[6]); a[7] = fmaf(f.y, c1, a[7]);
    }
    if (i < i1) {
        int s0 = g_srcl[i];
        float c0 = csrc[s0];
        uint4 v0 = *(const uint4*)(h1 + (size_t)s0 * 256 + lane * 8);
        float2 f;
        f = __half22float2(*(__half2*)&v0.x); a[0] = fmaf(f.x, c0, a[0]); a[1] = fmaf(f.y, c0, a[1]);
        f = __half22float2(*(__half2*)&v0.y); a[2] = fmaf(f.x, c0, a[2]); a[3] = fmaf(f.y, c0, a[3]);
        f = __half22float2(*(__half2*)&v0.z); a[4] = fmaf(f.x, c0, a[4]); a[5] = fmaf(f.y, c0, a[5]);
        f = __half22float2(*(__half2*)&v0.w); a[6] = fmaf(f.x, c0, a[6]); a[7] = fmaf(f.y, c0, a[7]);
    }
    {
        float c = cdst[node];
        const float4* bp = (const float4*)b1 + lane * 2;
        float4 b0 = bp[0], b1v = bp[1];
        float4 o0, o1;
        o0.x = fmaxf(fmaf(a[0], c, b0.x), 0.f);  o0.y = fmaxf(fmaf(a[1], c, b0.y), 0.f);
        o0.z = fmaxf(fmaf(a[2], c, b0.z), 0.f);  o0.w = fmaxf(fmaf(a[3], c, b0.w), 0.f);
        o1.x = fmaxf(fmaf(a[4], c, b1v.x), 0.f); o1.y = fmaxf(fmaf(a[5], c, b1v.y), 0.f);
        o1.z = fmaxf(fmaf(a[6], c, b1v.z), 0.f); o1.w = fmaxf(fmaf(a[7], c, b1v.w), 0.f);
        *(float4*)&x1s[wl][lane * 8]     = o0;
        *(float4*)&x1s[wl][lane * 8 + 4] = o1;
    }
    __syncwarp();
    float acc = 0.f;
    const float* xr = x1s[wl];
    #pragma unroll
    for (int k4 = 0; k4 < 64; k4++) {
        float4 x = *(const float4*)&xr[k4 * 4];
        int k = k4 * 4;
        acc = fmaf(x.x, W2s[(k + 0) * 32 + lane], acc);
        acc = fmaf(x.y, W2s[(k + 1) * 32 + lane], acc);
        acc = fmaf(x.z, W2s[(k + 2) * 32 + lane], acc);
        acc = fmaf(x.w, W2s[(k + 3) * 32 + lane], acc);
    }
    h2[(size_t)node * 32 + lane] = __float2half_rn(acc * csrc[node]);
}

// ---------------- fusedB: agg32(h2 fp16) + relu + GEMM3 -> h3 ---------------
__global__ __launch_bounds__(256)
void fusedB_kernel(const __half* __restrict__ h2, const float* __restrict__ W3,
                   const float* __restrict__ b2, float* __restrict__ h3,
                   const float* __restrict__ csrc, const float* __restrict__ cdst) {
    __shared__ float W3s[224];
    const int tid = threadIdx.x;
    if (tid < 224) W3s[tid] = W3[tid];
    __syncthreads();
    const int lane = tid & 31;
    const int node = (blockIdx.x * 256 + tid) >> 5;
    if (node >= NND) return;
    int i0 = g_off[node], i1 = g_off[node + 1];
    float a0 = 0.f, a1 = 0.f, a2 = 0.f, a3 = 0.f;
    int i = i0;
    for (; i + 4 <= i1; i += 4) {
        a0 += __half2float(h2[(size_t)g_srcl[i]     * 32 + lane]);
        a1 += __half2float(h2[(size_t)g_srcl[i + 1] * 32 + lane]);
        a2 += __half2float(h2[(size_t)g_srcl[i + 2] * 32 + lane]);
        a3 += __half2float(h2[(size_t)g_srcl[i + 3] * 32 + lane]);
    }
    for (; i < i1; i++) a0 += __half2float(h2[(size_t)g_srcl[i] * 32 + lane]);
    float x2 = fmaxf(fmaf((a0 + a1) + (a2 + a3), cdst[node], b2[lane]), 0.f);
    float s = csrc[node];
    float r[7];
    #pragma unroll
    for (int j = 0; j < 7; j++) {
        float v = x2 * W3s[lane * 7 + j];
        #pragma unroll
        for (int d = 16; d > 0; d >>= 1)
            v += __shfl_xor_sync(0xFFFFFFFFu, v, d);
        r[j] = v;
    }
    float outv = 0.f;
    #pragma unroll
    for (int j = 0; j < 7; j++) if (lane == j) outv = r[j];
    if (lane < 7) h3[(size_t)node * 8 + lane] = outv * s;
}

// ---------------- CSR aggregation F=7 + log_softmax -------------------------
__global__ __launch_bounds__(256)
void agg7_final_kernel(const float* __restrict__ h, const float* __restrict__ b3,
                       const float* __restrict__ cdst, float* __restrict__ out) {
    int warp = (blockIdx.x * blockDim.x + threadIdx.x) >> 5;
    int lane = threadIdx.x & 31;
    int sub  = lane & 7;
    int node = warp * 4 + (lane >> 3);
    if (node >= NND) return;
    int i0 = g_off[node], i1 = g_off[node + 1];
    float a = 0.f;
    if (sub < 7)
        for (int i = i0; i < i1; i++) a += h[(size_t)g_srcl[i] * 8 + sub];
    float v = (sub < 7) ? fmaf(a, cdst[node], b3[sub]) : -1e30f;
    float mx = v;
    #pragma unroll
    for (int d = 1; d < 8; d <<= 1)
        mx = fmaxf(mx, __shfl_xor_sync(0xFFFFFFFFu, mx, d));
    float e = (sub < 7) ? expf(v - mx) : 0.f;
    float se = e;
    #pragma unroll
    for (int d = 1; d < 8; d <<= 1)
        se += __shfl_xor_sync(0xFFFFFFFFu, se, d);
    float lse = logf(se);
    if (sub < 7) out[(size_t)node * 7 + sub] = v - mx - lse;
}

// ---------------- host ------------------------------------------------------
extern "C" void kernel_launch(void* const* d_in, const int* in_sizes, int n_in,
                              void* d_out, int out_size) {
    const float* feat = (const float*)d_in[0];
    const void*  edge = d_in[1];
    const float* W1   = (const float*)d_in[2];
    const float* b1   = (const float*)d_in[3];
    const float* W2   = (const float*)d_in[4];
    const float* b2   = (const float*)d_in[5];
    const float* W3   = (const float*)d_in[6];
    const float* b3   = (const float*)d_in[7];
    float* out = (float*)d_out;

    float *p_csrc, *p_cdst, *p_h3;
    __half *p_h1, *p_h2;
    signed char* p_Bq;
    cudaGetSymbolAddress((void**)&p_csrc, g_csrc);
    cudaGetSymbolAddress((void**)&p_cdst, g_cdst);
    cudaGetSymbolAddress((void**)&p_h1,   g_h1);
    cudaGetSymbolAddress((void**)&p_h2,   g_h2);
    cudaGetSymbolAddress((void**)&p_h3,   g_h3);
    cudaGetSymbolAddress((void**)&p_Bq,   g_Bq);

    static int inited = 0;
    static cudaStream_t s2;
    static cudaEvent_t evFork, evJoin;
    if (!inited) {
        cudaFuncSetAttribute(gemm1_s8, cudaFuncAttributeMaxDynamicSharedMemorySize, SMEM_G1);
        cudaStreamCreateWithFlags(&s2, cudaStreamNonBlocking);
        cudaEventCreateWithFlags(&evFork, cudaEventDisableTiming);
        cudaEventCreateWithFlags(&evJoin, cudaEventDisableTiming);
        inited = 1;
    }

    // fork immediately: both legs independent from t=0
    cudaEventRecord(evFork, 0);
    cudaStreamWaitEvent(s2, evFork, 0);

    // s2 leg: graph prep
    zero_detect_kernel<<<(NND + 255) / 256, 256, 0, s2>>>(edge);
    deg_kernel<<<1024, 256, 0, s2>>>(edge);
    scanA_kernel<<<NBS, 256, 0, s2>>>();
    scanC_kernel<<<NBS, 256, 0, s2>>>();
    fill_kernel<<<1024, 256, 0, s2>>>(edge);
    cudaEventRecord(evJoin, s2);

    // main leg: W1 transpose-quantize -> int8 gemm1
    {
        dim3 g(KP / 32, F1 / 32);
        convW1_kernel<<<g, 256>>>(W1);
    }
    gemm1_s8<<<(NND + 127) / 128, 512, SMEM_G1>>>(feat, p_Bq, p_h1);

    // join, then fused tail
    cudaStreamWaitEvent(0, evJoin, 0);
    fusedA_kernel<<<(NND + 31) / 32, 1024>>>(p_h1, W2, b1, p_h2, p_csrc, p_cdst);
    fusedB_kernel<<<(NND * 32 + 255) / 256, 256>>>(p_h2, W3, b2, p_h3, p_csrc, p_cdst);
    agg7_final_kernel<<<((NND + 3) / 4 * 32 + 255) / 256, 256>>>(p_h3, b3, p_cdst, out);
}

// round 13
// speedup vs baseline: 1.6645x; 1.6645x over previous
#include <cuda_runtime.h>
#include <cuda_fp16.h>
#include <cstdint>
#include <cstddef>

#define NND 50000
#define NED 800000
#define F0 1433
#define KP 1440            // 45 * 32
#define NKT 45
#define F1 256
#define F2 32
#define NBS 196            // scan blocks: 196*256 = 50176

#define SH_Q   16.0f       // h1 int8 scale
#define INV_SH 0.0625f

// ---------------- device scratch -------------------------------------------
__device__ float g_csrc[NND];
__device__ float g_cdst[NND];
__device__ signed char g_h1q[(size_t)NND * F1];
__device__ __half g_h2[(size_t)NND * F2];
__device__ float g_h3[(size_t)NND * 8];
__device__ int   g_is64;
__device__ int   g_degin[NND];
__device__ int   g_degout[NND];
__device__ int   g_off[NND + 1];
__device__ int   g_cur[NND];
__device__ int   g_srcl[NED];
__device__ int   g_bsum[NBS];
// W1^T as fp16: [n=256][k=KP]
__device__ __half g_Bt[(size_t)F1 * KP];

// ---------------- helpers ---------------------------------------------------
__device__ __forceinline__ int load_idx(const void* edge, int is64, long long lin) {
    if (is64) return (int)((const long long*)edge)[lin];
    return ((const int*)edge)[lin];
}
__device__ __forceinline__ void cpa16(uint32_t dst, const void* src) {
    asm volatile("cp.async.cg.shared.global [%0],[%1],16;" :: "r"(dst), "l"(src));
}
#define CP_COMMIT() asm volatile("cp.async.commit_group;")
#define CP_WAIT1()  asm volatile("cp.async.wait_group 1;" ::: "memory")

__device__ __forceinline__ void ldsm4(uint32_t& r0, uint32_t& r1, uint32_t& r2, uint32_t& r3, uint32_t a) {
    asm volatile("ldmatrix.sync.aligned.m8n8.x4.shared.b16 {%0,%1,%2,%3},[%4];"
                 : "=r"(r0), "=r"(r1), "=r"(r2), "=r"(r3) : "r"(a));
}
__device__ __forceinline__ void mma_f16(float* c, const uint32_t* a, uint32_t b0, uint32_t b1) {
    asm volatile("mma.sync.aligned.m16n8k16.row.col.f32.f16.f16.f32 "
                 "{%0,%1,%2,%3},{%4,%5,%6,%7},{%8,%9},{%0,%1,%2,%3};"
                 : "+f"(c[0]), "+f"(c[1]), "+f"(c[2]), "+f"(c[3])
                 : "r"(a[0]), "r"(a[1]), "r"(a[2]), "r"(a[3]), "r"(b0), "r"(b1));
}
__device__ __forceinline__ uint32_t smem_u32(const void* p) {
    uint32_t a;
    asm("{ .reg .u64 t; cvta.to.shared.u64 t, %1; cvt.u32.u64 %0, t; }" : "=r"(a) : "l"(p));
    return a;
}
__device__ __forceinline__ uint32_t pack_h2(float a, float b) {
    __half2 h = __floats2half2_rn(a, b);
    return *(uint32_t*)&h;
}

// ---------------- init: detect + zero degrees + convert W1^T ----------------
__global__ void init_kernel(const void* edge, const float* __restrict__ W1) {
    int i = blockIdx.x * blockDim.x + threadIdx.x;
    if (i == 0) {
        const unsigned long long* p = (const unsigned long long*)edge;
        int ok = 1;
        #pragma unroll
        for (int j = 0; j < 16; j++)
            if (p[j] >= (unsigned long long)NND) ok = 0;
        g_is64 = ok;
    }
    if (i < NND) { g_degin[i] = 0; g_degout[i] = 0; }
    if (i < F1 * KP) {
        int n = i / KP, k = i % KP;
        float x = (k < F0) ? W1[(size_t)k * F1 + n] : 0.f;
        g_Bt[i] = __float2half_rn(x);
    }
}

__global__ void deg_kernel(const void* edge) {
    int is64 = g_is64;
    int stride = gridDim.x * blockDim.x;
    for (int e = blockIdx.x * blockDim.x + threadIdx.x; e < NED; e += stride) {
        int s = load_idx(edge, is64, e);
        int d = load_idx(edge, is64, (long long)NED + e);
        atomicAdd(&g_degout[s], 1);
        atomicAdd(&g_degin[d], 1);
    }
}

// ---------------- 2-kernel coalesced scan -----------------------------------
__global__ __launch_bounds__(256) void scanA_kernel() {
    __shared__ int sd[256];
    int t = threadIdx.x, b = blockIdx.x;
    int idx = b * 256 + t;
    int d = (idx < NND) ? g_degin[idx] : 0;
    sd[t] = d; __syncthreads();
    #pragma unroll
    for (int s = 1; s < 256; s <<= 1) {
        int v = (t >= s) ? sd[t - s] : 0;
        __syncthreads();
        sd[t] += v;
        __syncthreads();
    }
    if (idx < NND) g_off[idx] = sd[t] - d;     // block-exclusive
    if (t == 255) g_bsum[b] = sd[255];
}
__global__ __launch_bounds__(256) void scanC_kernel() {
    __shared__ int sd[256];
    int t = threadIdx.x, b = blockIdx.x;
    sd[t] = (t < b) ? g_bsum[t] : 0;
    __syncthreads();
    #pragma unroll
    for (int s = 128; s > 0; s >>= 1) {
        if (t < s) sd[t] += sd[t + s];
        __syncthreads();
    }
    int pre = sd[0];
    int idx = b * 256 + t;
    if (idx < NND) {
        int off = g_off[idx] + pre;
        g_off[idx] = off;
        g_cur[idx] = off;
        g_csrc[idx] = rsqrtf((float)max(g_degout[idx], 1));
        g_cdst[idx] = rsqrtf((float)max(g_degin[idx], 1));
    }
    if (idx == 0) g_off[NND] = NED;
}

__global__ void fill_kernel(const void* edge) {
    int is64 = g_is64;
    int stride = gridDim.x * blockDim.x;
    for (int e = blockIdx.x * blockDim.x + threadIdx.x; e < NED; e += stride) {
        int s = load_idx(edge, is64, e);
        int d = load_idx(edge, is64, (long long)NED + e);
        int pos = atomicAdd(&g_cur[d], 1);
        g_srcl[pos] = s;
    }
}

// ---------------- GEMM1: fp16 mma.sync f32-acc, M=128 N=256, 3-stage --------
// (mainloop identical to the 315.5us R9 kernel; only the epilogue quantizes
//  h1 to int8 at scale SH_Q)
#define ASTR 80
#define SA_SZ (128 * ASTR)        /* 10240 */
#define SB_SZ (256 * ASTR)        /* 20480 */
#define STAGE (SA_SZ + SB_SZ)     /* 30720 */
#define SMEM_G1 (3 * STAGE)       /* 92160 */

extern __shared__ char g1s[];

__global__ __launch_bounds__(512, 1)
void gemm1_f16(const float* __restrict__ A, const __half* __restrict__ Bt,
               signed char* __restrict__ C)
{
    const int tid = threadIdx.x;
    const int l   = tid & 31;
    const int wid = tid >> 5;
    const int mw  = (wid & 1) * 64;
    const int nw  = (wid >> 1) * 32;
    const int bm  = blockIdx.x * 128;
    const uint32_t sb = smem_u32(g1s);

    const int a_row = tid >> 2, a_cg = tid & 3;
    const int a_grow = bm + a_row;
    const bool a_rv = (a_grow < NND);
    const float* a_base = A + (size_t)a_grow * F0 + a_cg * 8;

    float acc[4][4][4];
    #pragma unroll
    for (int t = 0; t < 4; t++)
        #pragma unroll
        for (int j = 0; j < 4; j++)
            #pragma unroll
            for (int q = 0; q < 4; q++) acc[t][j][q] = 0.f;

    float rA[8];
    auto ldgA = [&](int kt) {
        int c0 = kt * 32 + a_cg * 8;
        #pragma unroll
        for (int j = 0; j < 8; j++)
            rA[j] = (a_rv && (c0 + j) < F0) ? a_base[kt * 32 + j] : 0.f;
    };
    auto stsA = [&](int buf) {
        uint32_t w0 = pack_h2(rA[0], rA[1]);
        uint32_t w1 = pack_h2(rA[2], rA[3]);
        uint32_t w2 = pack_h2(rA[4], rA[5]);
        uint32_t w3 = pack_h2(rA[6], rA[7]);
        *(uint4*)(g1s + buf * STAGE + a_row * ASTR + a_cg * 16) = make_uint4(w0, w1, w2, w3);
    };
    auto cpB = [&](int kt, int buf) {
        #pragma unroll
        for (int i = 0; i < 2; i++) {
            int ch = tid * 2 + i;
            int n = ch >> 2, k16 = ch & 3;
            uint32_t dst = sb + (uint32_t)(buf * STAGE + SA_SZ + n * ASTR + k16 * 16);
            cpa16(dst, Bt + (size_t)n * KP + kt * 32 + k16 * 8);
        }
    };

    ldgA(0); cpB(0, 0); CP_COMMIT();
    stsA(0);
    ldgA(1); cpB(1, 1); CP_COMMIT();

    const int      lrow = ((l >> 3) & 1) * 8 + (l & 7);
    const uint32_t acol = (uint32_t)((l >> 4) * 16);
    const uint32_t brow = (uint32_t)(nw + ((l >> 4) & 1) * 8 + (l & 7));
    const uint32_t bcol = (uint32_t)(((l >> 3) & 1) * 16);

    for (int kt = 0; kt < NKT; kt++) {
        CP_WAIT1();
        __syncthreads();
        if (kt + 1 < NKT) stsA((kt + 1) % 3);
        if (kt + 2 < NKT) { cpB(kt + 2, (kt + 2) % 3); ldgA(kt + 2); }
        CP_COMMIT();

        const int buf = kt % 3;
        const uint32_t sa  = sb + (uint32_t)(buf * STAGE);
        const uint32_t sbb = sa + SA_SZ;

        #pragma unroll
        for (int ks = 0; ks < 2; ks++) {
            uint32_t bb[8];
            uint32_t ba = sbb + brow * ASTR + (uint32_t)(ks * 32) + bcol;
            ldsm4(bb[0], bb[1], bb[2], bb[3], ba);
            ldsm4(bb[4], bb[5], bb[6], bb[7], ba + 16 * ASTR);
            #pragma unroll
            for (int t = 0; t < 4; t++) {
                uint32_t aa[4];
                uint32_t aadr = sa + (uint32_t)((mw + t * 16 + lrow) * ASTR + ks * 32) + acol;
                ldsm4(aa[0], aa[1], aa[2], aa[3], aadr);
                mma_f16(acc[t][0], aa, bb[0], bb[1]);
                mma_f16(acc[t][1], aa, bb[2], bb[3]);
                mma_f16(acc[t][2], aa, bb[4], bb[5]);
                mma_f16(acc[t][3], aa, bb[6], bb[7]);
            }
        }
        __syncthreads();
    }

    // epilogue: quantize h1 to int8 (scale SH_Q)
    #pragma unroll
    for (int t = 0; t < 4; t++) {
        int r0 = bm + mw + t * 16 + (l >> 2);
        #pragma unroll
        for (int half = 0; half < 2; half++) {
            int row = r0 + half * 8;
            if (row < NND) {
                #pragma unroll
                for (int j = 0; j < 4; j++) {
                    int col = nw + j * 8 + (l & 3) * 2;
                    float v0 = acc[t][j][half * 2]     * SH_Q;
                    float v1 = acc[t][j][half * 2 + 1] * SH_Q;
                    int q0 = __float2int_rn(fminf(fmaxf(v0, -127.f), 127.f));
                    int q1 = __float2int_rn(fminf(fmaxf(v1, -127.f), 127.f));
                    char2 pk; pk.x = (char)q0; pk.y = (char)q1;
                    *(char2*)&C[(size_t)row * F1 + col] = pk;
                }
            }
        }
    }
}

// ---------------- fusedA: agg256(int8 h1 * csrc[s]) + relu + GEMM2 ----------
__global__ __launch_bounds__(1024)
void fusedA_kernel(const signed char* __restrict__ h1, const float* __restrict__ W2,
                   const float* __restrict__ b1, __half* __restrict__ h2,
                   const float* __restrict__ csrc, const float* __restrict__ cdst) {
    __shared__ float W2s[256 * 32];
    __shared__ float x1s[32][256];
    const int tid = threadIdx.x;
    for (int i = tid; i < 256 * 32; i += 1024) W2s[i] = W2[i];
    __syncthreads();

    const int wl   = tid >> 5;
    const int lane = tid & 31;
    const int node = blockIdx.x * 32 + wl;
    if (node >= NND) return;

    int i0 = g_off[node], i1 = g_off[node + 1];
    float a[8] = {0.f, 0.f, 0.f, 0.f, 0.f, 0.f, 0.f, 0.f};
    for (int i = i0; i < i1; i++) {
        int s0 = g_srcl[i];
        float c0 = csrc[s0] * INV_SH;
        uint2 v = *(const uint2*)(h1 + (size_t)s0 * 256 + lane * 8);
        int wx = (int)v.x, wy = (int)v.y;
        a[0] = fmaf((float)(signed char)(wx      ), c0, a[0]);
        a[1] = fmaf((float)(signed char)(wx >>  8), c0, a[1]);
        a[2] = fmaf((float)(signed char)(wx >> 16), c0, a[2]);
        a[3] = fmaf((float)(signed char)(wx >> 24), c0, a[3]);
        a[4] = fmaf((float)(signed char)(wy      ), c0, a[4]);
        a[5] = fmaf((float)(signed char)(wy >>  8), c0, a[5]);
        a[6] = fmaf((float)(signed char)(wy >> 16), c0, a[6]);
        a[7] = fmaf((float)(signed char)(wy >> 24), c0, a[7]);
    }
    {
        float c = cdst[node];
        const float4* bp = (const float4*)b1 + lane * 2;
        float4 b0 = bp[0], b1v = bp[1];
        float4 o0, o1;
        o0.x = fmaxf(fmaf(a[0], c, b0.x), 0.f);  o0.y = fmaxf(fmaf(a[1], c, b0.y), 0.f);
        o0.z = fmaxf(fmaf(a[2], c, b0.z), 0.f);  o0.w = fmaxf(fmaf(a[3], c, b0.w), 0.f);
        o1.x = fmaxf(fmaf(a[4], c, b1v.x), 0.f); o1.y = fmaxf(fmaf(a[5], c, b1v.y), 0.f);
        o1.z = fmaxf(fmaf(a[6], c, b1v.z), 0.f); o1.w = fmaxf(fmaf(a[7], c, b1v.w), 0.f);
        *(float4*)&x1s[wl][lane * 8]     = o0;
        *(float4*)&x1s[wl][lane * 8 + 4] = o1;
    }
    __syncwarp();
    float acc = 0.f;
    const float* xr = x1s[wl];
    #pragma unroll
    for (int k4 = 0; k4 < 64; k4++) {
        float4 x = *(const float4*)&xr[k4 * 4];
        int k = k4 * 4;
        acc = fmaf(x.x, W2s[(k + 0) * 32 + lane], acc);
        acc = fmaf(x.y, W2s[(k + 1) * 32 + lane], acc);
        acc = fmaf(x.z, W2s[(k + 2) * 32 + lane], acc);
        acc = fmaf(x.w, W2s[(k + 3) * 32 + lane], acc);
    }
    h2[(size_t)node * 32 + lane] = __float2half_rn(acc * csrc[node]);
}

// ---------------- fusedB: agg32(h2 fp16) + relu + GEMM3 -> h3 ---------------
__global__ __launch_bounds__(256)
void fusedB_kernel(const __half* __restrict__ h2, const float* __restrict__ W3,
                   const float* __restrict__ b2, float* __restrict__ h3,
                   const float* __restrict__ csrc, const float* __restrict__ cdst) {
    __shared__ float W3s[224];
    const int tid = threadIdx.x;
    if (tid < 224) W3s[tid] = W3[tid];
    __syncthreads();
    const int lane = tid & 31;
    const int node = (blockIdx.x * 256 + tid) >> 5;
    if (node >= NND) return;
    int i0 = g_off[node], i1 = g_off[node + 1];
    float a0 = 0.f, a1 = 0.f, a2 = 0.f, a3 = 0.f;
    int i = i0;
    for (; i + 4 <= i1; i += 4) {
        a0 += __half2float(h2[(size_t)g_srcl[i]     * 32 + lane]);
        a1 += __half2float(h2[(size_t)g_srcl[i + 1] * 32 + lane]);
        a2 += __half2float(h2[(size_t)g_srcl[i + 2] * 32 + lane]);
        a3 += __half2float(h2[(size_t)g_srcl[i + 3] * 32 + lane]);
    }
    for (; i < i1; i++) a0 += __half2float(h2[(size_t)g_srcl[i] * 32 + lane]);
    float x2 = fmaxf(fmaf((a0 + a1) + (a2 + a3), cdst[node], b2[lane]), 0.f);
    float s = csrc[node];
    float r[7];
    #pragma unroll
    for (int j = 0; j < 7; j++) {
        float v = x2 * W3s[lane * 7 + j];
        #pragma unroll
        for (int d = 16; d > 0; d >>= 1)
            v += __shfl_xor_sync(0xFFFFFFFFu, v, d);
        r[j] = v;
    }
    float outv = 0.f;
    #pragma unroll
    for (int j = 0; j < 7; j++) if (lane == j) outv = r[j];
    if (lane < 7) h3[(size_t)node * 8 + lane] = outv * s;
}

// ---------------- CSR aggregation F=7 + log_softmax -------------------------
__global__ __launch_bounds__(256)
void agg7_final_kernel(const float* __restrict__ h, const float* __restrict__ b3,
                       const float* __restrict__ cdst, float* __restrict__ out) {
    int warp = (blockIdx.x * blockDim.x + threadIdx.x) >> 5;
    int lane = threadIdx.x & 31;
    int sub  = lane & 7;
    int node = warp * 4 + (lane >> 3);
    if (node >= NND) return;
    int i0 = g_off[node], i1 = g_off[node + 1];
    float a = 0.f;
    if (sub < 7)
        for (int i = i0; i < i1; i++) a += h[(size_t)g_srcl[i] * 8 + sub];
    float v = (sub < 7) ? fmaf(a, cdst[node], b3[sub]) : -1e30f;
    float mx = v;
    #pragma unroll
    for (int d = 1; d < 8; d <<= 1)
        mx = fmaxf(mx, __shfl_xor_sync(0xFFFFFFFFu, mx, d));
    float e = (sub < 7) ? expf(v - mx) : 0.f;
    float se = e;
    #pragma unroll
    for (int d = 1; d < 8; d <<= 1)
        se += __shfl_xor_sync(0xFFFFFFFFu, se, d);
    float lse = logf(se);
    if (sub < 7) out[(size_t)node * 7 + sub] = v - mx - lse;
}

// ---------------- host ------------------------------------------------------
extern "C" void kernel_launch(void* const* d_in, const int* in_sizes, int n_in,
                              void* d_out, int out_size) {
    const float* feat = (const float*)d_in[0];
    const void*  edge = d_in[1];
    const float* W1   = (const float*)d_in[2];
    const float* b1   = (const float*)d_in[3];
    const float* W2   = (const float*)d_in[4];
    const float* b2   = (const float*)d_in[5];
    const float* W3   = (const float*)d_in[6];
    const float* b3   = (const float*)d_in[7];
    float* out = (float*)d_out;

    float *p_csrc, *p_cdst, *p_h3;
    __half *p_h2;
    signed char* p_h1q;
    __half* p_Bt;
    cudaGetSymbolAddress((void**)&p_csrc, g_csrc);
    cudaGetSymbolAddress((void**)&p_cdst, g_cdst);
    cudaGetSymbolAddress((void**)&p_h1q,  g_h1q);
    cudaGetSymbolAddress((void**)&p_h2,   g_h2);
    cudaGetSymbolAddress((void**)&p_h3,   g_h3);
    cudaGetSymbolAddress((void**)&p_Bt,   g_Bt);

    static int inited = 0;
    static cudaStream_t s2;
    static cudaEvent_t evFork, evJoin;
    if (!inited) {
        cudaFuncSetAttribute(gemm1_f16, cudaFuncAttributeMaxDynamicSharedMemorySize, SMEM_G1);
        cudaStreamCreateWithFlags(&s2, cudaStreamNonBlocking);
        cudaEventCreateWithFlags(&evFork, cudaEventDisableTiming);
        cudaEventCreateWithFlags(&evJoin, cudaEventDisableTiming);
        inited = 1;
    }

    // main stream: init (W1 conversion + degree zero + detect)
    init_kernel<<<(F1 * KP + 255) / 256, 256>>>(edge, W1);
    // fork: graph prep runs concurrent with gemm1
    cudaEventRecord(evFork, 0);
    cudaStreamWaitEvent(s2, evFork, 0);
    deg_kernel<<<1024, 256, 0, s2>>>(edge);
    scanA_kernel<<<NBS, 256, 0, s2>>>();
    scanC_kernel<<<NBS, 256, 0, s2>>>();
    fill_kernel<<<1024, 256, 0, s2>>>(edge);
    cudaEventRecord(evJoin, s2);

    // main stream: gemm1 (independent of graph prep)
    gemm1_f16<<<(NND + 127) / 128, 512, SMEM_G1>>>(feat, p_Bt, p_h1q);

    // join, then fused tail
    cudaStreamWaitEvent(0, evJoin, 0);
    fusedA_kernel<<<(NND + 31) / 32, 1024>>>(p_h1q, W2, b1, p_h2, p_csrc, p_cdst);
    fusedB_kernel<<<(NND * 32 + 255) / 256, 256>>>(p_h2, W3, b2, p_h3, p_csrc, p_cdst);
    agg7_final_kernel<<<((NND + 3) / 4 * 32 + 255) / 256, 256>>>(p_h3, b3, p_cdst, out);
}

// round 14
// speedup vs baseline: 1.7252x; 1.0365x over previous
#include <cuda_runtime.h>
#include <cuda_fp16.h>
#include <cstdint>
#include <cstddef>

#define NND 50000
#define NED 800000
#define F0 1433
#define KP 1440            // 45 * 32
#define NKT 45
#define F1 256
#define F2 32
#define NBS 196            // scan blocks: 196*256 = 50176

// ---------------- device scratch -------------------------------------------
__device__ float g_csrc[NND];
__device__ float g_cdst[NND];
__device__ __half g_h1[(size_t)NND * F1];
__device__ __half g_h2[(size_t)NND * F2];
__device__ float g_h3[(size_t)NND * 8];
__device__ int   g_is64;
__device__ int   g_degin[NND];
__device__ int   g_degout[NND];
__device__ int   g_off[NND + 1];
__device__ int   g_cur[NND];
__device__ int   g_srcl[NED];
__device__ int   g_bsum[NBS];
// W1^T as fp16: [n=256][k=KP]
__device__ __half g_Bt[(size_t)F1 * KP];

// ---------------- helpers ---------------------------------------------------
__device__ __forceinline__ int load_idx(const void* edge, int is64, long long lin) {
    if (is64) return (int)((const long long*)edge)[lin];
    return ((const int*)edge)[lin];
}
__device__ __forceinline__ void cpa16(uint32_t dst, const void* src) {
    asm volatile("cp.async.cg.shared.global [%0],[%1],16;" :: "r"(dst), "l"(src));
}
#define CP_COMMIT() asm volatile("cp.async.commit_group;")
#define CP_WAIT1()  asm volatile("cp.async.wait_group 1;" ::: "memory")

__device__ __forceinline__ void ldsm4(uint32_t& r0, uint32_t& r1, uint32_t& r2, uint32_t& r3, uint32_t a) {
    asm volatile("ldmatrix.sync.aligned.m8n8.x4.shared.b16 {%0,%1,%2,%3},[%4];"
                 : "=r"(r0), "=r"(r1), "=r"(r2), "=r"(r3) : "r"(a));
}
__device__ __forceinline__ void mma_f16(float* c, const uint32_t* a, uint32_t b0, uint32_t b1) {
    asm volatile("mma.sync.aligned.m16n8k16.row.col.f32.f16.f16.f32 "
                 "{%0,%1,%2,%3},{%4,%5,%6,%7},{%8,%9},{%0,%1,%2,%3};"
                 : "+f"(c[0]), "+f"(c[1]), "+f"(c[2]), "+f"(c[3])
                 : "r"(a[0]), "r"(a[1]), "r"(a[2]), "r"(a[3]), "r"(b0), "r"(b1));
}
__device__ __forceinline__ uint32_t smem_u32(const void* p) {
    uint32_t a;
    asm("{ .reg .u64 t; cvta.to.shared.u64 t, %1; cvt.u32.u64 %0, t; }" : "=r"(a) : "l"(p));
    return a;
}
__device__ __forceinline__ uint32_t pack_h2(float a, float b) {
    __half2 h = __floats2half2_rn(a, b);
    return *(uint32_t*)&h;
}

// ---------------- init: detect + zero degrees + convert W1^T ----------------
__global__ void init_kernel(const void* edge, const float* __restrict__ W1) {
    int i = blockIdx.x * blockDim.x + threadIdx.x;
    if (i == 0) {
        const unsigned long long* p = (const unsigned long long*)edge;
        int ok = 1;
        #pragma unroll
        for (int j = 0; j < 16; j++)
            if (p[j] >= (unsigned long long)NND) ok = 0;
        g_is64 = ok;
    }
    if (i < NND) { g_degin[i] = 0; g_degout[i] = 0; }
    if (i < F1 * KP) {
        int n = i / KP, k = i % KP;
        float x = (k < F0) ? W1[(size_t)k * F1 + n] : 0.f;
        g_Bt[i] = __float2half_rn(x);
    }
}

__global__ void deg_kernel(const void* edge) {
    int is64 = g_is64;
    int stride = gridDim.x * blockDim.x;
    for (int e = blockIdx.x * blockDim.x + threadIdx.x; e < NED; e += stride) {
        int s = load_idx(edge, is64, e);
        int d = load_idx(edge, is64, (long long)NED + e);
        atomicAdd(&g_degout[s], 1);
        atomicAdd(&g_degin[d], 1);
    }
}

// ---------------- 2-kernel coalesced scan -----------------------------------
__global__ __launch_bounds__(256) void scanA_kernel() {
    __shared__ int sd[256];
    int t = threadIdx.x, b = blockIdx.x;
    int idx = b * 256 + t;
    int d = (idx < NND) ? g_degin[idx] : 0;
    sd[t] = d; __syncthreads();
    #pragma unroll
    for (int s = 1; s < 256; s <<= 1) {
        int v = (t >= s) ? sd[t - s] : 0;
        __syncthreads();
        sd[t] += v;
        __syncthreads();
    }
    if (idx < NND) g_off[idx] = sd[t] - d;     // block-exclusive
    if (t == 255) g_bsum[b] = sd[255];
}
__global__ __launch_bounds__(256) void scanC_kernel() {
    __shared__ int sd[256];
    int t = threadIdx.x, b = blockIdx.x;
    sd[t] = (t < b) ? g_bsum[t] : 0;
    __syncthreads();
    #pragma unroll
    for (int s = 128; s > 0; s >>= 1) {
        if (t < s) sd[t] += sd[t + s];
        __syncthreads();
    }
    int pre = sd[0];
    int idx = b * 256 + t;
    if (idx < NND) {
        int off = g_off[idx] + pre;
        g_off[idx] = off;
        g_cur[idx] = off;
        g_csrc[idx] = rsqrtf((float)max(g_degout[idx], 1));
        g_cdst[idx] = rsqrtf((float)max(g_degin[idx], 1));
    }
    if (idx == 0) g_off[NND] = NED;
}

__global__ void fill_kernel(const void* edge) {
    int is64 = g_is64;
    int stride = gridDim.x * blockDim.x;
    for (int e = blockIdx.x * blockDim.x + threadIdx.x; e < NED; e += stride) {
        int s = load_idx(edge, is64, e);
        int d = load_idx(edge, is64, (long long)NED + e);
        int pos = atomicAdd(&g_cur[d], 1);
        g_srcl[pos] = s;
    }
}

// ---------------- GEMM1: fp16 mma.sync f32-acc, M=128 N=256, 3-stage --------
#define ASTR 80
#define SA_SZ (128 * ASTR)        /* 10240 */
#define SB_SZ (256 * ASTR)        /* 20480 */
#define STAGE (SA_SZ + SB_SZ)     /* 30720 */
#define SMEM_G1 (3 * STAGE)       /* 92160 */

extern __shared__ char g1s[];

__global__ __launch_bounds__(512, 1)
void gemm1_f16(const float* __restrict__ A, const __half* __restrict__ Bt,
               __half* __restrict__ C)
{
    const int tid = threadIdx.x;
    const int l   = tid & 31;
    const int wid = tid >> 5;
    const int mw  = (wid & 1) * 64;
    const int nw  = (wid >> 1) * 32;
    const int bm  = blockIdx.x * 128;
    const uint32_t sb = smem_u32(g1s);

    const int a_row = tid >> 2, a_cg = tid & 3;
    const int a_grow = bm + a_row;
    const bool a_rv = (a_grow < NND);
    const float* a_base = A + (size_t)a_grow * F0 + a_cg * 8;

    float acc[4][4][4];
    #pragma unroll
    for (int t = 0; t < 4; t++)
        #pragma unroll
        for (int j = 0; j < 4; j++)
            #pragma unroll
            for (int q = 0; q < 4; q++) acc[t][j][q] = 0.f;

    float rA[8];
    auto ldgA = [&](int kt) {
        int c0 = kt * 32 + a_cg * 8;
        #pragma unroll
        for (int j = 0; j < 8; j++)
            rA[j] = (a_rv && (c0 + j) < F0) ? a_base[kt * 32 + j] : 0.f;
    };
    auto stsA = [&](int buf) {
        uint32_t w0 = pack_h2(rA[0], rA[1]);
        uint32_t w1 = pack_h2(rA[2], rA[3]);
        uint32_t w2 = pack_h2(rA[4], rA[5]);
        uint32_t w3 = pack_h2(rA[6], rA[7]);
        *(uint4*)(g1s + buf * STAGE + a_row * ASTR + a_cg * 16) = make_uint4(w0, w1, w2, w3);
    };
    auto cpB = [&](int kt, int buf) {
        #pragma unroll
        for (int i = 0; i < 2; i++) {
            int ch = tid * 2 + i;
            int n = ch >> 2, k16 = ch & 3;
            uint32_t dst = sb + (uint32_t)(buf * STAGE + SA_SZ + n * ASTR + k16 * 16);
            cpa16(dst, Bt + (size_t)n * KP + kt * 32 + k16 * 8);
        }
    };

    ldgA(0); cpB(0, 0); CP_COMMIT();
    stsA(0);
    ldgA(1); cpB(1, 1); CP_COMMIT();

    const int      lrow = ((l >> 3) & 1) * 8 + (l & 7);
    const uint32_t acol = (uint32_t)((l >> 4) * 16);
    const uint32_t brow = (uint32_t)(nw + ((l >> 4) & 1) * 8 + (l & 7));
    const uint32_t bcol = (uint32_t)(((l >> 3) & 1) * 16);

    for (int kt = 0; kt < NKT; kt++) {
        CP_WAIT1();
        __syncthreads();
        if (kt + 1 < NKT) stsA((kt + 1) % 3);
        if (kt + 2 < NKT) { cpB(kt + 2, (kt + 2) % 3); ldgA(kt + 2); }
        CP_COMMIT();

        const int buf = kt % 3;
        const uint32_t sa  = sb + (uint32_t)(buf * STAGE);
        const uint32_t sbb = sa + SA_SZ;

        #pragma unroll
        for (int ks = 0; ks < 2; ks++) {
            uint32_t bb[8];
            uint32_t ba = sbb + brow * ASTR + (uint32_t)(ks * 32) + bcol;
            ldsm4(bb[0], bb[1], bb[2], bb[3], ba);
            ldsm4(bb[4], bb[5], bb[6], bb[7], ba + 16 * ASTR);
            #pragma unroll
            for (int t = 0; t < 4; t++) {
                uint32_t aa[4];
                uint32_t aadr = sa + (uint32_t)((mw + t * 16 + lrow) * ASTR + ks * 32) + acol;
                ldsm4(aa[0], aa[1], aa[2], aa[3], aadr);
                mma_f16(acc[t][0], aa, bb[0], bb[1]);
                mma_f16(acc[t][1], aa, bb[2], bb[3]);
                mma_f16(acc[t][2], aa, bb[4], bb[5]);
                mma_f16(acc[t][3], aa, bb[6], bb[7]);
            }
        }
        __syncthreads();
    }

    #pragma unroll
    for (int t = 0; t < 4; t++) {
        int r0 = bm + mw + t * 16 + (l >> 2);
        #pragma unroll
        for (int half = 0; half < 2; half++) {
            int row = r0 + half * 8;
            if (row < NND) {
                #pragma unroll
                for (int j = 0; j < 4; j++) {
                    int col = nw + j * 8 + (l & 3) * 2;
                    __half2 v = __floats2half2_rn(acc[t][j][half * 2],
                                                  acc[t][j][half * 2 + 1]);
                    *(__half2*)&C[(size_t)row * F1 + col] = v;
                }
            }
        }
    }
}

// ---------------- fusedA: agg256(h1*csrc[s]) + relu + GEMM2 -> h2 fp16 ------
// 4-wide unrolled gather loop for higher MLP
__global__ __launch_bounds__(1024)
void fusedA_kernel(const __half* __restrict__ h1, const float* __restrict__ W2,
                   const float* __restrict__ b1, __half* __restrict__ h2,
                   const float* __restrict__ csrc, const float* __restrict__ cdst) {
    __shared__ float W2s[256 * 32];
    __shared__ float x1s[32][256];
    const int tid = threadIdx.x;
    for (int i = tid; i < 256 * 32; i += 1024) W2s[i] = W2[i];
    __syncthreads();

    const int wl   = tid >> 5;
    const int lane = tid & 31;
    const int node = blockIdx.x * 32 + wl;
    if (node >= NND) return;

    int i0 = g_off[node], i1 = g_off[node + 1];
    float a[8] = {0.f, 0.f, 0.f, 0.f, 0.f, 0.f, 0.f, 0.f};

    auto accum = [&](uint4 v, float c) {
        float2 f;
        f = __half22float2(*(__half2*)&v.x); a[0] = fmaf(f.x, c, a[0]); a[1] = fmaf(f.y, c, a[1]);
        f = __half22float2(*(__half2*)&v.y); a[2] = fmaf(f.x, c, a[2]); a[3] = fmaf(f.y, c, a[3]);
        f = __half22float2(*(__half2*)&v.z); a[4] = fmaf(f.x, c, a[4]); a[5] = fmaf(f.y, c, a[5]);
        f = __half22float2(*(__half2*)&v.w); a[6] = fmaf(f.x, c, a[6]); a[7] = fmaf(f.y, c, a[7]);
    };

    int i = i0;
    for (; i + 4 <= i1; i += 4) {
        int s0 = g_srcl[i], s1 = g_srcl[i + 1], s2 = g_srcl[i + 2], s3 = g_srcl[i + 3];
        float c0 = csrc[s0], c1 = csrc[s1], c2 = csrc[s2], c3 = csrc[s3];
        uint4 v0 = *(const uint4*)(h1 + (size_t)s0 * 256 + lane * 8);
        uint4 v1 = *(const uint4*)(h1 + (size_t)s1 * 256 + lane * 8);
        uint4 v2 = *(const uint4*)(h1 + (size_t)s2 * 256 + lane * 8);
        uint4 v3 = *(const uint4*)(h1 + (size_t)s3 * 256 + lane * 8);
        accum(v0, c0); accum(v1, c1); accum(v2, c2); accum(v3, c3);
    }
    for (; i < i1; i++) {
        int s0 = g_srcl[i];
        float c0 = csrc[s0];
        uint4 v0 = *(const uint4*)(h1 + (size_t)s0 * 256 + lane * 8);
        accum(v0, c0);
    }
    {
        float c = cdst[node];
        const float4* bp = (const float4*)b1 + lane * 2;
        float4 b0 = bp[0], b1v = bp[1];
        float4 o0, o1;
        o0.x = fmaxf(fmaf(a[0], c, b0.x), 0.f);  o0.y = fmaxf(fmaf(a[1], c, b0.y), 0.f);
        o0.z = fmaxf(fmaf(a[2], c, b0.z), 0.f);  o0.w = fmaxf(fmaf(a[3], c, b0.w), 0.f);
        o1.x = fmaxf(fmaf(a[4], c, b1v.x), 0.f); o1.y = fmaxf(fmaf(a[5], c, b1v.y), 0.f);
        o1.z = fmaxf(fmaf(a[6], c, b1v.z), 0.f); o1.w = fmaxf(fmaf(a[7], c, b1v.w), 0.f);
        *(float4*)&x1s[wl][lane * 8]     = o0;
        *(float4*)&x1s[wl][lane * 8 + 4] = o1;
    }
    __syncwarp();
    float acc = 0.f;
    const float* xr = x1s[wl];
    #pragma unroll
    for (int k4 = 0; k4 < 64; k4++) {
        float4 x = *(const float4*)&xr[k4 * 4];
        int k = k4 * 4;
        acc = fmaf(x.x, W2s[(k + 0) * 32 + lane], acc);
        acc = fmaf(x.y, W2s[(k + 1) * 32 + lane], acc);
        acc = fmaf(x.z, W2s[(k + 2) * 32 + lane], acc);
        acc = fmaf(x.w, W2s[(k + 3) * 32 + lane], acc);
    }
    h2[(size_t)node * 32 + lane] = __float2half_rn(acc * csrc[node]);
}

// ---------------- fusedB: agg32(h2 fp16) + relu + GEMM3 -> h3 ---------------
__global__ __launch_bounds__(256)
void fusedB_kernel(const __half* __restrict__ h2, const float* __restrict__ W3,
                   const float* __restrict__ b2, float* __restrict__ h3,
                   const float* __restrict__ csrc, const float* __restrict__ cdst) {
    __shared__ float W3s[224];
    const int tid = threadIdx.x;
    if (tid < 224) W3s[tid] = W3[tid];
    __syncthreads();
    const int lane = tid & 31;
    const int node = (blockIdx.x * 256 + tid) >> 5;
    if (node >= NND) return;
    int i0 = g_off[node], i1 = g_off[node + 1];
    float a0 = 0.f, a1 = 0.f, a2 = 0.f, a3 = 0.f;
    int i = i0;
    for (; i + 4 <= i1; i += 4) {
        a0 += __half2float(h2[(size_t)g_srcl[i]     * 32 + lane]);
        a1 += __half2float(h2[(size_t)g_srcl[i + 1] * 32 + lane]);
        a2 += __half2float(h2[(size_t)g_srcl[i + 2] * 32 + lane]);
        a3 += __half2float(h2[(size_t)g_srcl[i + 3] * 32 + lane]);
    }
    for (; i < i1; i++) a0 += __half2float(h2[(size_t)g_srcl[i] * 32 + lane]);
    float x2 = fmaxf(fmaf((a0 + a1) + (a2 + a3), cdst[node], b2[lane]), 0.f);
    float s = csrc[node];
    float r[7];
    #pragma unroll
    for (int j = 0; j < 7; j++) {
        float v = x2 * W3s[lane * 7 + j];
        #pragma unroll
        for (int d = 16; d > 0; d >>= 1)
            v += __shfl_xor_sync(0xFFFFFFFFu, v, d);
        r[j] = v;
    }
    float outv = 0.f;
    #pragma unroll
    for (int j = 0; j < 7; j++) if (lane == j) outv = r[j];
    if (lane < 7) h3[(size_t)node * 8 + lane] = outv * s;
}

// ---------------- CSR aggregation F=7 + log_softmax -------------------------
__global__ __launch_bounds__(256)
void agg7_final_kernel(const float* __restrict__ h, const float* __restrict__ b3,
                       const float* __restrict__ cdst, float* __restrict__ out) {
    int warp = (blockIdx.x * blockDim.x + threadIdx.x) >> 5;
    int lane = threadIdx.x & 31;
    int sub  = lane & 7;
    int node = warp * 4 + (lane >> 3);
    if (node >= NND) return;
    int i0 = g_off[node], i1 = g_off[node + 1];
    float a = 0.f;
    if (sub < 7)
        for (int i = i0; i < i1; i++) a += h[(size_t)g_srcl[i] * 8 + sub];
    float v = (sub < 7) ? fmaf(a, cdst[node], b3[sub]) : -1e30f;
    float mx = v;
    #pragma unroll
    for (int d = 1; d < 8; d <<= 1)
        mx = fmaxf(mx, __shfl_xor_sync(0xFFFFFFFFu, mx, d));
    float e = (sub < 7) ? expf(v - mx) : 0.f;
    float se = e;
    #pragma unroll
    for (int d = 1; d < 8; d <<= 1)
        se += __shfl_xor_sync(0xFFFFFFFFu, se, d);
    float lse = logf(se);
    if (sub < 7) out[(size_t)node * 7 + sub] = v - mx - lse;
}

// ---------------- host ------------------------------------------------------
extern "C" void kernel_launch(void* const* d_in, const int* in_sizes, int n_in,
                              void* d_out, int out_size) {
    const float* feat = (const float*)d_in[0];
    const void*  edge = d_in[1];
    const float* W1   = (const float*)d_in[2];
    const float* b1   = (const float*)d_in[3];
    const float* W2   = (const float*)d_in[4];
    const float* b2   = (const float*)d_in[5];
    const float* W3   = (const float*)d_in[6];
    const float* b3   = (const float*)d_in[7];
    float* out = (float*)d_out;

    float *p_csrc, *p_cdst, *p_h3;
    __half *p_h1, *p_h2, *p_Bt;
    cudaGetSymbolAddress((void**)&p_csrc, g_csrc);
    cudaGetSymbolAddress((void**)&p_cdst, g_cdst);
    cudaGetSymbolAddress((void**)&p_h1,   g_h1);
    cudaGetSymbolAddress((void**)&p_h2,   g_h2);
    cudaGetSymbolAddress((void**)&p_h3,   g_h3);
    cudaGetSymbolAddress((void**)&p_Bt,   g_Bt);

    static int inited = 0;
    static cudaStream_t s2;
    static cudaEvent_t evFork, evJoin;
    if (!inited) {
        cudaFuncSetAttribute(gemm1_f16, cudaFuncAttributeMaxDynamicSharedMemorySize, SMEM_G1);
        cudaStreamCreateWithFlags(&s2, cudaStreamNonBlocking);
        cudaEventCreateWithFlags(&evFork, cudaEventDisableTiming);
        cudaEventCreateWithFlags(&evJoin, cudaEventDisableTiming);
        inited = 1;
    }

    // main stream: init (W1 conversion + degree zero + detect)
    init_kernel<<<(F1 * KP + 255) / 256, 256>>>(edge, W1);
    // fork: graph prep runs concurrent with gemm1
    cudaEventRecord(evFork, 0);
    cudaStreamWaitEvent(s2, evFork, 0);
    deg_kernel<<<1024, 256, 0, s2>>>(edge);
    scanA_kernel<<<NBS, 256, 0, s2>>>();
    scanC_kernel<<<NBS, 256, 0, s2>>>();
    fill_kernel<<<1024, 256, 0, s2>>>(edge);
    cudaEventRecord(evJoin, s2);

    // main stream: gemm1 (independent of graph prep)
    gemm1_f16<<<(NND + 127) / 128, 512, SMEM_G1>>>(feat, p_Bt, p_h1);

    // join, then fused tail
    cudaStreamWaitEvent(0, evJoin, 0);
    fusedA_kernel<<<(NND + 31) / 32, 1024>>>(p_h1, W2, b1, p_h2, p_csrc, p_cdst);
    fusedB_kernel<<<(NND * 32 + 255) / 256, 256>>>(p_h2, W3, b2, p_h3, p_csrc, p_cdst);
    agg7_final_kernel<<<((NND + 3) / 4 * 32 + 255) / 256, 256>>>(p_h3, b3, p_cdst, out);
}